// round 15
// baseline (speedup 1.0000x reference)
#include <cuda_runtime.h>
#include <cuda_bf16.h>
#include <math.h>

#define TT    1024
#define NBAT  64
#define KD    512
#define G3    1536
#define SHP   520         // smem h pitch (elements)
#define NGRP  4           // independent batch groups
#define GR    16          // batch rows per group
#define CCTA  32          // column-CTAs per group
#define UNITS 16          // hidden units per CTA
#define COLS  64          // G-cols per CTA (4 gate-planes x 16 units)
#define NCTA  (NGRP * CCTA)   // 128

// ---- static device scratch ----
__device__ float          g_GX[(size_t)TT * NBAT * G3];
__device__ __nv_bfloat16  g_H_hi[(size_t)(TT + 1) * NBAT * KD];
__device__ __nv_bfloat16  g_H_lo[(size_t)(TT + 1) * NBAT * KD];
__device__ __nv_bfloat16  g_X_hi[(size_t)NBAT * TT * KD];
__device__ __nv_bfloat16  g_X_lo[(size_t)NBAT * TT * KD];
__device__ float          g_Whp[G3 * KD];
__device__ float          g_bpf[G3];
__device__ __nv_bfloat16  g_Mp_hi[CCTA * COLS * KD];
__device__ __nv_bfloat16  g_Mp_lo[CCTA * COLS * KD];
__device__ float          g_biasA[CCTA * COLS];
__device__ float          g_bias0[CCTA * COLS];
__device__ __nv_bfloat16  g_Wx_hi[G3 * KD];
__device__ __nv_bfloat16  g_Wx_lo[G3 * KD];
__device__ __nv_bfloat16  g_Wp_hi[256 * KD];
__device__ __nv_bfloat16  g_Wp_lo[256 * KD];
__device__ __align__(128) unsigned g_flag[NCTA];   // per-CTA step flags

__device__ __forceinline__ void split2(float v, __nv_bfloat16 &hi, __nv_bfloat16 &lo) {
    hi = __float2bfloat16(v);
    lo = __float2bfloat16(v - __bfloat162float(hi));
}

__device__ __forceinline__ void mma_bf16(float *d, const unsigned *a, const unsigned *b) {
    asm volatile(
        "mma.sync.aligned.m16n8k16.row.col.f32.bf16.bf16.f32 "
        "{%0,%1,%2,%3}, {%4,%5,%6,%7}, {%8,%9}, {%0,%1,%2,%3};\n"
        : "+f"(d[0]), "+f"(d[1]), "+f"(d[2]), "+f"(d[3])
        : "r"(a[0]), "r"(a[1]), "r"(a[2]), "r"(a[3]), "r"(b[0]), "r"(b[1]));
}

__device__ __forceinline__ unsigned smem_u32(const void *p) {
    return (unsigned)__cvta_generic_to_shared(p);
}

__device__ __forceinline__ void cp16(unsigned s, const void *g) {
    asm volatile("cp.async.cg.shared.global [%0], [%1], 16;\n" :: "r"(s), "l"(g));
}
#define CP_COMMIT() asm volatile("cp.async.commit_group;\n" ::: "memory")
#define CP_WAIT(n)  asm volatile("cp.async.wait_group %0;\n" :: "n"(n) : "memory")

__device__ __forceinline__ void ldsm4(unsigned *r, unsigned addr) {
    asm volatile("ldmatrix.sync.aligned.m8n8.x4.shared.b16 {%0,%1,%2,%3}, [%4];\n"
        : "=r"(r[0]), "=r"(r[1]), "=r"(r[2]), "=r"(r[3]) : "r"(addr));
}

__device__ __forceinline__ void st_rel_gpu(unsigned *p, unsigned v) {
    asm volatile("st.release.gpu.u32 [%0], %1;\n" :: "l"(p), "r"(v) : "memory");
}

__device__ __forceinline__ unsigned ld_acq_gpu(const unsigned *p) {
    unsigned v;
    asm volatile("ld.acquire.gpu.u32 %0, [%1];\n" : "=r"(v) : "l"(p) : "memory");
    return v;
}

// ---- prep 1: W_hp = W_pf @ W_p ; bpf = W_pf @ b_p ----
__global__ void k_prep1(const float *__restrict__ Wih, const float *__restrict__ Wp,
                        const float *__restrict__ bp) {
    int idx = blockIdx.x * blockDim.x + threadIdx.x;
    if (idx < G3 * KD) {
        int j = idx >> 9, k = idx & 511;
        const float *wrow = Wih + (size_t)j * 768 + 512;
        float acc = 0.f;
#pragma unroll 4
        for (int p = 0; p < 256; p++) acc += wrow[p] * Wp[p * KD + k];
        g_Whp[idx] = acc;
        return;
    }
    int j = idx - G3 * KD;
    if (j < G3) {
        const float *wrow = Wih + (size_t)j * 768 + 512;
        float acc = 0.f;
        for (int p = 0; p < 256; p++) acc += wrow[p] * bp[p];
        g_bpf[j] = acc;
    }
}

// ---- prep 2: pack Mp/biases, split Wx, split Wp, split X, init h0/flags ----
#define P0 (CCTA * COLS * KD)
#define P1 (G3 * KD)
#define P2 (256 * KD)
#define P3 ((size_t)NBAT * TT * KD)
#define P4 (NBAT * KD)
__global__ void k_prep2(const float *__restrict__ Wih, const float *__restrict__ Whh,
                        const float *__restrict__ bih, const float *__restrict__ bhh,
                        const float *__restrict__ Wp, const float *__restrict__ X) {
    size_t idx = (size_t)blockIdx.x * blockDim.x + threadIdx.x;

    if (idx < P0) {                                   // Mp + biases
        int k = (int)idx & 511;
        int c = ((int)idx >> 9) & 63;                 // column within CTA (COLS=64)
        int cb = (int)(idx >> 15);                    // column-CTA id 0..31
        int gsel = c >> 4, jj = c & 15;
        int j = cb * 16 + jj;
        float v;
        if (gsel == 0)      v = Whh[j * KD + k] + g_Whp[j * KD + k];
        else if (gsel == 1) v = Whh[(512 + j) * KD + k] + g_Whp[(512 + j) * KD + k];
        else if (gsel == 2) v = g_Whp[(1024 + j) * KD + k];
        else                v = Whh[(1024 + j) * KD + k];
        __nv_bfloat16 hi, lo;
        split2(v, hi, lo);
        g_Mp_hi[idx] = hi;
        g_Mp_lo[idx] = lo;
        if (k == 0) {
            float bb, b0;
            if (gsel == 0)      { b0 = bih[j] + bhh[j];             bb = b0 + g_bpf[j]; }
            else if (gsel == 1) { b0 = bih[512 + j] + bhh[512 + j]; bb = b0 + g_bpf[512 + j]; }
            else if (gsel == 2) { b0 = bih[1024 + j];               bb = b0 + g_bpf[1024 + j]; }
            else                { b0 = bhh[1024 + j];               bb = b0; }
            g_biasA[cb * COLS + c] = bb;
            g_bias0[cb * COLS + c] = b0;
        }
        return;
    }
    idx -= P0;

    if (idx < P1) {                                   // Wx split
        int j = (int)(idx >> 9), k = (int)idx & 511;
        __nv_bfloat16 hi, lo;
        split2(Wih[(size_t)j * 768 + k], hi, lo);
        g_Wx_hi[idx] = hi;
        g_Wx_lo[idx] = lo;
        return;
    }
    idx -= P1;

    if (idx < P2) {                                   // Wp split
        __nv_bfloat16 hi, lo;
        split2(Wp[idx], hi, lo);
        g_Wp_hi[idx] = hi;
        g_Wp_lo[idx] = lo;
        return;
    }
    idx -= P2;

    if (idx < P3) {                                   // X split
        __nv_bfloat16 hi, lo;
        split2(X[idx], hi, lo);
        g_X_hi[idx] = hi;
        g_X_lo[idx] = lo;
        return;
    }
    idx -= P3;

    if (idx < P4) {                                   // h slot 0 = 0
        g_H_hi[idx] = __float2bfloat16(0.f);
        g_H_lo[idx] = __float2bfloat16(0.f);
        return;
    }
    idx -= P4;
    if (idx < NCTA) g_flag[idx] = 0u;                 // step flags
}

// ---- GX = X @ Wx^T : grid (24,1024) x 256 threads, 64x64 tiles ----
__global__ void __launch_bounds__(256) k_gx() {
    int w = threadIdx.x >> 5, lane = threadIdx.x & 31;
    int g = lane >> 2, tg = lane & 3;
    int m0 = blockIdx.y * 64 + (w >> 1) * 16;
    int n0 = blockIdx.x * 64 + (w & 1) * 32;

    float acc[4][4];
#pragma unroll
    for (int i = 0; i < 4; i++)
#pragma unroll
        for (int q = 0; q < 4; q++) acc[i][q] = 0.f;

    const __nv_bfloat16 *a0h = g_X_hi + (size_t)(m0 + g) * KD;
    const __nv_bfloat16 *a1h = g_X_hi + (size_t)(m0 + g + 8) * KD;
    const __nv_bfloat16 *a0l = g_X_lo + (size_t)(m0 + g) * KD;
    const __nv_bfloat16 *a1l = g_X_lo + (size_t)(m0 + g + 8) * KD;

#pragma unroll 2
    for (int kc = 0; kc < KD; kc += 16) {
        unsigned ah[4], al[4];
        ah[0] = *(const unsigned *)(a0h + kc + tg * 2);
        ah[1] = *(const unsigned *)(a1h + kc + tg * 2);
        ah[2] = *(const unsigned *)(a0h + kc + tg * 2 + 8);
        ah[3] = *(const unsigned *)(a1h + kc + tg * 2 + 8);
        al[0] = *(const unsigned *)(a0l + kc + tg * 2);
        al[1] = *(const unsigned *)(a1l + kc + tg * 2);
        al[2] = *(const unsigned *)(a0l + kc + tg * 2 + 8);
        al[3] = *(const unsigned *)(a1l + kc + tg * 2 + 8);
#pragma unroll
        for (int nt = 0; nt < 4; nt++) {
            int col = n0 + nt * 8 + g;
            const __nv_bfloat16 *bh = g_Wx_hi + (size_t)col * KD + kc + tg * 2;
            const __nv_bfloat16 *bl = g_Wx_lo + (size_t)col * KD + kc + tg * 2;
            unsigned bhi[2] = { *(const unsigned *)bh, *(const unsigned *)(bh + 8) };
            unsigned blo[2] = { *(const unsigned *)bl, *(const unsigned *)(bl + 8) };
            mma_bf16(acc[nt], ah, bhi);
            mma_bf16(acc[nt], ah, blo);
            mma_bf16(acc[nt], al, bhi);
        }
    }

    int ma = m0 + g, mb = m0 + g + 8;
    size_t ra = (size_t)((ma & 1023) * 64 + (ma >> 10)) * G3;
    size_t rb = (size_t)((mb & 1023) * 64 + (mb >> 10)) * G3;
#pragma unroll
    for (int nt = 0; nt < 4; nt++) {
        int col = n0 + nt * 8 + tg * 2;
        *(float2 *)(g_GX + ra + col) = make_float2(acc[nt][0], acc[nt][1]);
        *(float2 *)(g_GX + rb + col) = make_float2(acc[nt][2], acc[nt][3]);
    }
}

// ---- recurrence v5: 4 groups x 32 CTAs, 16 rows/group, 16 units/CTA ----
// smem (bytes):
//   sWb   [0, 131072)        packed b-frags: [plane][sub(8)][kc32][lane] uint2
//   sHhi  [131072, 147712)   16 x 520 bf16
//   sHlo  [147712, 164352)   16 x 520 bf16
//   sG    [164352, 168704)   16 x 68 float
//   sBias [168704, 168960) ; sBias0 [168960, 169216)
#define REC_SMEM 169216

__global__ void __launch_bounds__(256) k_rec() {
    extern __shared__ char smem[];
    uint2         *sWb  = (uint2 *)(smem);
    __nv_bfloat16 *sHhi = (__nv_bfloat16 *)(smem + 131072);
    __nv_bfloat16 *sHlo = (__nv_bfloat16 *)(smem + 147712);
    float         *sG   = (float *)(smem + 164352);
    float         *sBias  = (float *)(smem + 168704);
    float         *sBias0 = (float *)(smem + 168960);

    int bx  = blockIdx.x;
    int cb  = bx & 31;        // column-CTA id
    int gid = bx >> 5;        // batch group id
    int tid = threadIdx.x;
    int w = tid >> 5, lane = tid & 31;
    int qd = lane >> 2, tg = lane & 3;

    // one-time: pack b-frags [plane][sub][kci][lane]
    for (int idx = tid; idx < 16384; idx += 256) {
        int pl    = idx & 31;
        int kci   = (idx >> 5) & 31;
        int sub   = (idx >> 10) & 7;
        int plane = idx >> 13;
        int c  = sub * 8 + (pl >> 2);
        int k0 = kci * 16 + (pl & 3) * 2;
        const __nv_bfloat16 *row =
            (plane ? g_Mp_lo : g_Mp_hi) + (size_t)cb * (COLS * KD) + c * KD;
        unsigned v0 = *(const unsigned *)(row + k0);
        unsigned v1 = *(const unsigned *)(row + k0 + 8);
        sWb[idx] = make_uint2(v0, v1);
    }
    if (tid < COLS) {
        sBias[tid]  = g_biasA[cb * COLS + tid];
        sBias0[tid] = g_bias0[cb * COLS + tid];
    }
    __syncthreads();

    // warp mma identity: warp w owns n8-subtile w (cols w*8..w*8+8), all 16 rows
    int tile = lane >> 3;
    int lrow = ((tile & 1) << 3) + (lane & 7);
    int lcb  = (tile >> 1) * 8;
    unsigned aHiB = smem_u32(sHhi) + (unsigned)(lrow * SHP + lcb) * 2;
    unsigned aLoB = smem_u32(sHlo) + (unsigned)(lrow * SHP + lcb) * 2;
    const uint2 *wbH = sWb + (0 * 8 + w) * 1024 + lane;
    const uint2 *wbL = sWb + (8 + w) * 1024 + lane;

    unsigned sHhiU = smem_u32(sHhi);
    unsigned sHloU = smem_u32(sHlo);

    // gate identity: 1 item/thread (16 rows x 16 units)
    int n_loc = tid >> 4, jj = tid & 15;
    int jglob = cb * 16 + jj;
    int nglob = gid * 16 + n_loc;
    unsigned *myflag   = &g_flag[gid * 32 + cb];
    unsigned *pollflag = &g_flag[gid * 32 + lane];

    for (int t = 0; t < TT; t++) {
        // prefetch GX gate operands (hidden under the MMA phase)
        const float *GXt = g_GX + (size_t)t * (NBAT * G3);
        float gx_r = GXt[nglob * G3 + jglob];
        float gx_z = GXt[nglob * G3 + 512 + jglob];
        float gx_n = GXt[nglob * G3 + 1024 + jglob];

        const char *Hh = (const char *)g_H_hi + (size_t)t * 65536 + gid * 16 * 1024;
        const char *Hl = (const char *)g_H_lo + (size_t)t * 65536 + gid * 16 * 1024;

        // stage group h slab (16 rows x 512 x 2 planes = 32KB), two K-halves
#pragma unroll
        for (int half = 0; half < 2; half++) {
#pragma unroll
            for (int it = 0; it < 4; it++) {
                int q = tid + it * 256;
                int plane = q >> 9;
                int r = q & 511;
                int row = r >> 5, ch = r & 31;
                const char *gsrc = (plane ? Hl : Hh) + row * 1024 + half * 512 + ch * 16;
                unsigned sdst = (plane ? sHloU : sHhiU)
                              + (unsigned)(row * (SHP * 2) + half * 512 + ch * 16);
                cp16(sdst, gsrc);
            }
            CP_COMMIT();
        }

        float accA[4] = {0.f, 0.f, 0.f, 0.f};
        float accB[4] = {0.f, 0.f, 0.f, 0.f};
        float accC[4] = {0.f, 0.f, 0.f, 0.f};
        unsigned ah[2][4], al[2][4];

        CP_WAIT(1);
        __syncthreads();
        ldsm4(ah[0], aHiB);
        ldsm4(al[0], aLoB);
#pragma unroll
        for (int kk = 0; kk < 16; kk++) {
            int p = kk & 1, pn = p ^ 1;
            if (kk < 15) {
                ldsm4(ah[pn], aHiB + (kk + 1) * 32);
                ldsm4(al[pn], aLoB + (kk + 1) * 32);
            }
            uint2 bh = wbH[kk * 32];
            uint2 bl = wbL[kk * 32];
            mma_bf16(accA, ah[p], (const unsigned *)&bh);
            mma_bf16(accB, ah[p], (const unsigned *)&bl);
            mma_bf16(accC, al[p], (const unsigned *)&bh);
        }

        CP_WAIT(0);
        __syncthreads();
        ldsm4(ah[0], aHiB + 16 * 32);
        ldsm4(al[0], aLoB + 16 * 32);
#pragma unroll
        for (int kk = 16; kk < 32; kk++) {
            int p = kk & 1, pn = p ^ 1;
            if (kk < 31) {
                ldsm4(ah[pn], aHiB + (kk + 1) * 32);
                ldsm4(al[pn], aLoB + (kk + 1) * 32);
            }
            uint2 bh = wbH[kk * 32];
            uint2 bl = wbL[kk * 32];
            mma_bf16(accA, ah[p], (const unsigned *)&bh);
            mma_bf16(accB, ah[p], (const unsigned *)&bl);
            mma_bf16(accC, al[p], (const unsigned *)&bh);
        }

        // epilogue: acc -> sG (pitch 68)
        {
            int c = w * 8 + tg * 2;
            sG[qd * 68 + c]           = accA[0] + accB[0] + accC[0];
            sG[qd * 68 + c + 1]       = accA[1] + accB[1] + accC[1];
            sG[(qd + 8) * 68 + c]     = accA[2] + accB[2] + accC[2];
            sG[(qd + 8) * 68 + c + 1] = accA[3] + accB[3] + accC[3];
        }
        __syncthreads();

        // gates (1 item/thread)
        {
            const float *bias = (t == 0) ? sBias0 : sBias;
            float pr = sG[n_loc * 68 + jj]       + gx_r + bias[jj];
            float pz = sG[n_loc * 68 + 16 + jj]  + gx_z + bias[16 + jj];
            float pi = sG[n_loc * 68 + 32 + jj]  + gx_n + bias[32 + jj];
            float ph = sG[n_loc * 68 + 48 + jj]         + bias[48 + jj];
            float r = 1.f / (1.f + __expf(-pr));
            float z = 1.f / (1.f + __expf(-pz));
            float ex = __expf(2.f * (pi + r * ph));
            float gg = __fdividef(ex - 1.f, ex + 1.f);
            float hold = __bfloat162float(sHhi[n_loc * SHP + jglob])
                       + __bfloat162float(sHlo[n_loc * SHP + jglob]);
            float hn = (1.f - z) * gg + z * hold;
            __nv_bfloat16 hi, lo;
            split2(hn, hi, lo);
            size_t oidx = (size_t)(t + 1) * (NBAT * KD) + (size_t)nglob * KD + jglob;
            g_H_hi[oidx] = hi;
            g_H_lo[oidx] = lo;
        }

        // group barrier: per-CTA release flag + 32-lane coalesced poll
        __syncthreads();
        if (w == 0) {
            if (lane == 0) st_rel_gpu(myflag, (unsigned)(t + 1));
            unsigned v;
            do { v = ld_acq_gpu(pollflag); }
            while (!__all_sync(0xffffffffu, v >= (unsigned)(t + 1)));
        }
        __syncthreads();
    }
}

// ---- out[n][t][p] = h_t @ Wp^T + b_p : grid (4,1024) x 256 threads ----
__global__ void __launch_bounds__(256) k_out(const float *__restrict__ bp,
                                             float *__restrict__ out) {
    int w = threadIdx.x >> 5, lane = threadIdx.x & 31;
    int g = lane >> 2, tg = lane & 3;
    int m0 = blockIdx.y * 64 + (w >> 1) * 16;   // m = t*64 + n
    int n0 = blockIdx.x * 64 + (w & 1) * 32;

    float acc[4][4];
#pragma unroll
    for (int i = 0; i < 4; i++)
#pragma unroll
        for (int q = 0; q < 4; q++) acc[i][q] = 0.f;

    const __nv_bfloat16 *a0h = g_H_hi + (size_t)(m0 + g + 64) * KD;
    const __nv_bfloat16 *a1h = g_H_hi + (size_t)(m0 + g + 8 + 64) * KD;
    const __nv_bfloat16 *a0l = g_H_lo + (size_t)(m0 + g + 64) * KD;
    const __nv_bfloat16 *a1l = g_H_lo + (size_t)(m0 + g + 8 + 64) * KD;

#pragma unroll 2
    for (int kc = 0; kc < KD; kc += 16) {
        unsigned ah[4], al[4];
        ah[0] = *(const unsigned *)(a0h + kc + tg * 2);
        ah[1] = *(const unsigned *)(a1h + kc + tg * 2);
        ah[2] = *(const unsigned *)(a0h + kc + tg * 2 + 8);
        ah[3] = *(const unsigned *)(a1h + kc + tg * 2 + 8);
        al[0] = *(const unsigned *)(a0l + kc + tg * 2);
        al[1] = *(const unsigned *)(a1l + kc + tg * 2);
        al[2] = *(const unsigned *)(a0l + kc + tg * 2 + 8);
        al[3] = *(const unsigned *)(a1l + kc + tg * 2 + 8);
#pragma unroll
        for (int nt = 0; nt < 4; nt++) {
            int col = n0 + nt * 8 + g;
            const __nv_bfloat16 *bh = g_Wp_hi + (size_t)col * KD + kc + tg * 2;
            const __nv_bfloat16 *bl = g_Wp_lo + (size_t)col * KD + kc + tg * 2;
            unsigned bhi[2] = { *(const unsigned *)bh, *(const unsigned *)(bh + 8) };
            unsigned blo[2] = { *(const unsigned *)bl, *(const unsigned *)(bl + 8) };
            mma_bf16(acc[nt], ah, bhi);
            mma_bf16(acc[nt], ah, blo);
            mma_bf16(acc[nt], al, bhi);
        }
    }

    int ma = m0 + g, mb = m0 + g + 8;
    size_t ra = (size_t)(ma & 63) * (TT * 256) + (size_t)(ma >> 6) * 256;
    size_t rb = (size_t)(mb & 63) * (TT * 256) + (size_t)(mb >> 6) * 256;
#pragma unroll
    for (int nt = 0; nt < 4; nt++) {
        int col = n0 + nt * 8 + tg * 2;
        float b0 = bp[col], b1 = bp[col + 1];
        *(float2 *)(out + ra + col) = make_float2(acc[nt][0] + b0, acc[nt][1] + b1);
        *(float2 *)(out + rb + col) = make_float2(acc[nt][2] + b0, acc[nt][3] + b1);
    }
}

extern "C" void kernel_launch(void* const* d_in, const int* in_sizes, int n_in,
                              void* d_out, int out_size) {
    const float *X   = (const float *)d_in[0];
    // d_in[1] = text_lengths (all == T; reference ignores them)
    const float *Wih = (const float *)d_in[2];
    const float *Whh = (const float *)d_in[3];
    const float *bih = (const float *)d_in[4];
    const float *bhh = (const float *)d_in[5];
    const float *Wp  = (const float *)d_in[6];
    const float *bp  = (const float *)d_in[7];
    float *out = (float *)d_out;

    static int smem_set = 0;
    if (!smem_set) {
        cudaFuncSetAttribute(k_rec, cudaFuncAttributeMaxDynamicSharedMemorySize, REC_SMEM);
        smem_set = 1;
    }

    int n1 = G3 * KD + G3;
    k_prep1<<<(n1 + 255) / 256, 256>>>(Wih, Wp, bp);

    size_t n2 = (size_t)P0 + P1 + P2 + P3 + P4 + NCTA;
    k_prep2<<<(unsigned)((n2 + 255) / 256), 256>>>(Wih, Whh, bih, bhh, Wp, X);

    dim3 ggx(24, 1024);
    k_gx<<<ggx, 256>>>();

    k_rec<<<NCTA, 256, REC_SMEM>>>();

    dim3 gout(4, 1024);
    k_out<<<gout, 256>>>(bp, out);
}

// round 16
// speedup vs baseline: 1.2090x; 1.2090x over previous
#include <cuda_runtime.h>
#include <cuda_bf16.h>
#include <math.h>

#define TT   1024
#define NBAT 64
#define KD   512
#define G3   1536
#define SHP  520          // smem h pitch (elements)
#define NCTA 128          // recurrence CTAs (4 hidden units each)

// ---- static device scratch ----
__device__ float          g_GX[(size_t)TT * NBAT * G3];
__device__ __nv_bfloat16  g_H_hi[(size_t)(TT + 1) * NBAT * KD];
__device__ __nv_bfloat16  g_H_lo[(size_t)(TT + 1) * NBAT * KD];
__device__ __nv_bfloat16  g_X_hi[(size_t)NBAT * TT * KD];
__device__ __nv_bfloat16  g_X_lo[(size_t)NBAT * TT * KD];
__device__ float          g_Whp[G3 * KD];
__device__ float          g_bpf[G3];
__device__ __nv_bfloat16  g_Mp_hi[NCTA * 16 * KD];
__device__ __nv_bfloat16  g_Mp_lo[NCTA * 16 * KD];
__device__ float          g_biasA[NCTA * 16];
__device__ float          g_bias0[NCTA * 16];
__device__ __nv_bfloat16  g_Wx_hi[G3 * KD];
__device__ __nv_bfloat16  g_Wx_lo[G3 * KD];
__device__ __nv_bfloat16  g_Wp_hi[256 * KD];
__device__ __nv_bfloat16  g_Wp_lo[256 * KD];
__device__ unsigned       g_cnt[TT];    // per-step arrival counters (self-cleaning)
__device__ unsigned       g_ep[TT];     // per-step epoch broadcast words
__device__ unsigned       g_fin;        // final cleanup round

__device__ __forceinline__ void split2(float v, __nv_bfloat16 &hi, __nv_bfloat16 &lo) {
    hi = __float2bfloat16(v);
    lo = __float2bfloat16(v - __bfloat162float(hi));
}

__device__ __forceinline__ void mma_bf16(float *d, const unsigned *a, const unsigned *b) {
    asm volatile(
        "mma.sync.aligned.m16n8k16.row.col.f32.bf16.bf16.f32 "
        "{%0,%1,%2,%3}, {%4,%5,%6,%7}, {%8,%9}, {%0,%1,%2,%3};\n"
        : "+f"(d[0]), "+f"(d[1]), "+f"(d[2]), "+f"(d[3])
        : "r"(a[0]), "r"(a[1]), "r"(a[2]), "r"(a[3]), "r"(b[0]), "r"(b[1]));
}

__device__ __forceinline__ unsigned smem_u32(const void *p) {
    return (unsigned)__cvta_generic_to_shared(p);
}

__device__ __forceinline__ void cp16(unsigned s, const void *g) {
    asm volatile("cp.async.cg.shared.global [%0], [%1], 16;\n" :: "r"(s), "l"(g));
}
#define CP_COMMIT() asm volatile("cp.async.commit_group;\n" ::: "memory")
#define CP_WAIT(n)  asm volatile("cp.async.wait_group %0;\n" :: "n"(n) : "memory")

__device__ __forceinline__ void ldsm4(unsigned *r, unsigned addr) {
    asm volatile("ldmatrix.sync.aligned.m8n8.x4.shared.b16 {%0,%1,%2,%3}, [%4];\n"
        : "=r"(r[0]), "=r"(r[1]), "=r"(r[2]), "=r"(r[3]) : "r"(addr));
}

__device__ __forceinline__ unsigned atom_add_gpu(unsigned *p, unsigned v) {
    unsigned old;
    asm volatile("atom.relaxed.gpu.add.u32 %0, [%1], %2;\n"
                 : "=r"(old) : "l"(p), "r"(v) : "memory");
    return old;
}

__device__ __forceinline__ void st_rel_gpu(unsigned *p, unsigned v) {
    asm volatile("st.release.gpu.u32 [%0], %1;\n" :: "l"(p), "r"(v) : "memory");
}

__device__ __forceinline__ unsigned ld_acq_gpu(const unsigned *p) {
    unsigned v;
    asm volatile("ld.acquire.gpu.u32 %0, [%1];\n" : "=r"(v) : "l"(p) : "memory");
    return v;
}

// ---- prep 1: W_hp = W_pf @ W_p ; bpf = W_pf @ b_p ----
__global__ void k_prep1(const float *__restrict__ Wih, const float *__restrict__ Wp,
                        const float *__restrict__ bp) {
    int idx = blockIdx.x * blockDim.x + threadIdx.x;
    if (idx < G3 * KD) {
        int j = idx >> 9, k = idx & 511;
        const float *wrow = Wih + (size_t)j * 768 + 512;
        float acc = 0.f;
#pragma unroll 4
        for (int p = 0; p < 256; p++) acc += wrow[p] * Wp[p * KD + k];
        g_Whp[idx] = acc;
        return;
    }
    int j = idx - G3 * KD;
    if (j < G3) {
        const float *wrow = Wih + (size_t)j * 768 + 512;
        float acc = 0.f;
        for (int p = 0; p < 256; p++) acc += wrow[p] * bp[p];
        g_bpf[j] = acc;
    }
}

// ---- prep 2: pack Mp/biases, split Wx, split Wp, split X, init h0/barriers ----
#define P0 (NCTA * 16 * KD)
#define P1 (G3 * KD)
#define P2 (256 * KD)
#define P3 ((size_t)NBAT * TT * KD)
#define P4 (NBAT * KD)
__global__ void k_prep2(const float *__restrict__ Wih, const float *__restrict__ Whh,
                        const float *__restrict__ bih, const float *__restrict__ bhh,
                        const float *__restrict__ Wp, const float *__restrict__ X) {
    size_t idx = (size_t)blockIdx.x * blockDim.x + threadIdx.x;

    if (idx < P0) {                                   // Mp + biases
        int k = (int)idx & 511;
        int c = ((int)idx >> 9) & 15;
        int b = (int)(idx >> 13);
        int gsel = c >> 2, jj = c & 3;
        int j = b * 4 + jj;
        float v;
        if (gsel == 0)      v = Whh[j * KD + k] + g_Whp[j * KD + k];
        else if (gsel == 1) v = Whh[(512 + j) * KD + k] + g_Whp[(512 + j) * KD + k];
        else if (gsel == 2) v = g_Whp[(1024 + j) * KD + k];
        else                v = Whh[(1024 + j) * KD + k];
        __nv_bfloat16 hi, lo;
        split2(v, hi, lo);
        g_Mp_hi[idx] = hi;
        g_Mp_lo[idx] = lo;
        if (k == 0) {
            float bb, b0;
            if (gsel == 0)      { b0 = bih[j] + bhh[j];             bb = b0 + g_bpf[j]; }
            else if (gsel == 1) { b0 = bih[512 + j] + bhh[512 + j]; bb = b0 + g_bpf[512 + j]; }
            else if (gsel == 2) { b0 = bih[1024 + j];               bb = b0 + g_bpf[1024 + j]; }
            else                { b0 = bhh[1024 + j];               bb = b0; }
            g_biasA[b * 16 + c] = bb;
            g_bias0[b * 16 + c] = b0;
        }
        return;
    }
    idx -= P0;

    if (idx < P1) {                                   // Wx split
        int j = (int)(idx >> 9), k = (int)idx & 511;
        __nv_bfloat16 hi, lo;
        split2(Wih[(size_t)j * 768 + k], hi, lo);
        g_Wx_hi[idx] = hi;
        g_Wx_lo[idx] = lo;
        return;
    }
    idx -= P1;

    if (idx < P2) {                                   // Wp split
        __nv_bfloat16 hi, lo;
        split2(Wp[idx], hi, lo);
        g_Wp_hi[idx] = hi;
        g_Wp_lo[idx] = lo;
        return;
    }
    idx -= P2;

    if (idx < P3) {                                   // X split
        __nv_bfloat16 hi, lo;
        split2(X[idx], hi, lo);
        g_X_hi[idx] = hi;
        g_X_lo[idx] = lo;
        return;
    }
    idx -= P3;

    if (idx < P4) {                                   // h slot 0 = 0
        g_H_hi[idx] = __float2bfloat16(0.f);
        g_H_lo[idx] = __float2bfloat16(0.f);
        return;
    }
    idx -= P4;
    if (idx < TT) { g_cnt[idx] = 0u; return; }        // arrival counters
    idx -= TT;
    if (idx < TT) { g_ep[idx] = 0u; return; }         // epoch words
    if (idx == TT) g_fin = 0u;
}

// ---- GX = X @ Wx^T : grid (24,1024) x 256 threads, 64x64 tiles ----
__global__ void __launch_bounds__(256) k_gx() {
    int w = threadIdx.x >> 5, lane = threadIdx.x & 31;
    int g = lane >> 2, tg = lane & 3;
    int m0 = blockIdx.y * 64 + (w >> 1) * 16;
    int n0 = blockIdx.x * 64 + (w & 1) * 32;

    float acc[4][4];
#pragma unroll
    for (int i = 0; i < 4; i++)
#pragma unroll
        for (int q = 0; q < 4; q++) acc[i][q] = 0.f;

    const __nv_bfloat16 *a0h = g_X_hi + (size_t)(m0 + g) * KD;
    const __nv_bfloat16 *a1h = g_X_hi + (size_t)(m0 + g + 8) * KD;
    const __nv_bfloat16 *a0l = g_X_lo + (size_t)(m0 + g) * KD;
    const __nv_bfloat16 *a1l = g_X_lo + (size_t)(m0 + g + 8) * KD;

#pragma unroll 2
    for (int kc = 0; kc < KD; kc += 16) {
        unsigned ah[4], al[4];
        ah[0] = *(const unsigned *)(a0h + kc + tg * 2);
        ah[1] = *(const unsigned *)(a1h + kc + tg * 2);
        ah[2] = *(const unsigned *)(a0h + kc + tg * 2 + 8);
        ah[3] = *(const unsigned *)(a1h + kc + tg * 2 + 8);
        al[0] = *(const unsigned *)(a0l + kc + tg * 2);
        al[1] = *(const unsigned *)(a1l + kc + tg * 2);
        al[2] = *(const unsigned *)(a0l + kc + tg * 2 + 8);
        al[3] = *(const unsigned *)(a1l + kc + tg * 2 + 8);
#pragma unroll
        for (int nt = 0; nt < 4; nt++) {
            int col = n0 + nt * 8 + g;
            const __nv_bfloat16 *bh = g_Wx_hi + (size_t)col * KD + kc + tg * 2;
            const __nv_bfloat16 *bl = g_Wx_lo + (size_t)col * KD + kc + tg * 2;
            unsigned bhi[2] = { *(const unsigned *)bh, *(const unsigned *)(bh + 8) };
            unsigned blo[2] = { *(const unsigned *)bl, *(const unsigned *)(bl + 8) };
            mma_bf16(acc[nt], ah, bhi);
            mma_bf16(acc[nt], ah, blo);
            mma_bf16(acc[nt], al, bhi);
        }
    }

    int ma = m0 + g, mb = m0 + g + 8;
    size_t ra = (size_t)((ma & 1023) * 64 + (ma >> 10)) * G3;
    size_t rb = (size_t)((mb & 1023) * 64 + (mb >> 10)) * G3;
#pragma unroll
    for (int nt = 0; nt < 4; nt++) {
        int col = n0 + nt * 8 + tg * 2;
        *(float2 *)(g_GX + ra + col) = make_float2(acc[nt][0], acc[nt][1]);
        *(float2 *)(g_GX + rb + col) = make_float2(acc[nt][2], acc[nt][3]);
    }
}

// ---- recurrence v6: 128 CTAs x 256 threads, pair-decoupled staging ----
// smem (bytes):
//   sWb   [0, 32768)       packed b-frags: [plane][nt][kc32][lane] uint2
//   sHhi  [32768, 99328)   64 x 520 bf16
//   sHlo  [99328, 165888)  64 x 520 bf16
//   sG    [165888, 170240) 64 x 17 float
//   sBias [170240, 170304) ; sBias0 [170304, 170368)
#define REC_SMEM 170368

__global__ void __launch_bounds__(256) k_rec() {
    extern __shared__ char smem[];
    uint2         *sWb  = (uint2 *)(smem);
    __nv_bfloat16 *sHhi = (__nv_bfloat16 *)(smem + 32768);
    __nv_bfloat16 *sHlo = (__nv_bfloat16 *)(smem + 99328);
    float         *sG   = (float *)(smem + 165888);
    float         *sBias  = (float *)(smem + 170240);
    float         *sBias0 = (float *)(smem + 170304);

    int b = blockIdx.x;
    int tid = threadIdx.x;
    int w = tid >> 5, lane = tid & 31;
    int g = lane >> 2, tg = lane & 3;

    // one-time: pack b-frags [plane][nt][kci][lane]
    for (int idx = tid; idx < 4096; idx += 256) {
        int pl   = idx & 31;
        int kci  = (idx >> 5) & 31;
        int nt_  = (idx >> 10) & 1;
        int plane= idx >> 11;
        int c  = nt_ * 8 + (pl >> 2);
        int k0 = kci * 16 + (pl & 3) * 2;
        const __nv_bfloat16 *row =
            (plane ? g_Mp_lo : g_Mp_hi) + (size_t)b * 8192 + c * 512;
        unsigned v0 = *(const unsigned *)(row + k0);
        unsigned v1 = *(const unsigned *)(row + k0 + 8);
        sWb[((plane * 2 + nt_) * 32 + kci) * 32 + pl] = make_uint2(v0, v1);
    }
    if (tid < 16) {
        sBias[tid]  = g_biasA[b * 16 + tid];
        sBias0[tid] = g_bias0[b * 16 + tid];
    }
    __syncthreads();

    // warp identity: m-pair mp = w>>1 (rows mp*16..mp*16+16), n-group nt = w&1
    int mp = w >> 1;
    int nt = w & 1;
    int m0 = mp * 16;
    int tile = lane >> 3;
    int lrow = m0 + ((tile & 1) << 3) + (lane & 7);
    int lcb  = (tile >> 1) * 8;
    unsigned aHiB = smem_u32(sHhi) + (unsigned)(lrow * SHP + lcb) * 2;
    unsigned aLoB = smem_u32(sHlo) + (unsigned)(lrow * SHP + lcb) * 2;
    const uint2 *wbH = sWb + (0 * 2 + nt) * 1024 + lane;
    const uint2 *wbL = sWb + (1 * 2 + nt) * 1024 + lane;

    // staging identity: warp stages its pair's 16 rows, one plane (nt0=hi, nt1=lo)
    unsigned stBase = (nt ? smem_u32(sHlo) : smem_u32(sHhi)) + (unsigned)m0 * (SHP * 2);
    const char *stSrcBase = (const char *)(nt ? g_H_lo : g_H_hi) + (size_t)m0 * 1024;

    // gate identity: 1 item/thread
    int gn = tid >> 2, gjj = tid & 3;
    int gj = b * 4 + gjj;

    for (int t = 0; t < TT; t++) {
        // prefetch GX gate operands (DRAM latency hides under staging + MMA)
        const float *GXt = g_GX + (size_t)t * (NBAT * G3);
        float gx_r = GXt[gn * G3 + gj];
        float gx_z = GXt[gn * G3 + 512 + gj];
        float gx_n = GXt[gn * G3 + 1024 + gj];

        // stage this pair's 16 rows of one plane: 32 cp16/lane (16KB/warp)
        const char *Hsrc = stSrcBase + (size_t)t * 65536;
#pragma unroll 8
        for (int i = 0; i < 32; i++) {
            int q = i * 32 + lane;
            int row = q >> 6, ch = q & 63;
            cp16(stBase + row * (SHP * 2) + ch * 16, Hsrc + row * 1024 + ch * 16);
        }
        CP_COMMIT();
        CP_WAIT(0);
        asm volatile("bar.sync %0, 64;\n" :: "r"(1 + mp) : "memory");

        float accA[4] = {0.f, 0.f, 0.f, 0.f};
        float accB[4] = {0.f, 0.f, 0.f, 0.f};
        float accC[4] = {0.f, 0.f, 0.f, 0.f};
        unsigned ah[2][4], al[2][4];

        ldsm4(ah[0], aHiB);
        ldsm4(al[0], aLoB);
#pragma unroll 8
        for (int kk = 0; kk < 32; kk++) {
            int p2 = kk & 1, pn = p2 ^ 1;
            if (kk < 31) {
                ldsm4(ah[pn], aHiB + (kk + 1) * 32);
                ldsm4(al[pn], aLoB + (kk + 1) * 32);
            }
            uint2 bh = wbH[kk * 32];
            uint2 bl = wbL[kk * 32];
            mma_bf16(accA, ah[p2], (const unsigned *)&bh);
            mma_bf16(accB, ah[p2], (const unsigned *)&bl);
            mma_bf16(accC, al[p2], (const unsigned *)&bh);
        }

        // epilogue: acc -> sG (pitch 17)
        {
            int c = nt * 8 + tg * 2;
            sG[(m0 + g) * 17 + c]         = accA[0] + accB[0] + accC[0];
            sG[(m0 + g) * 17 + c + 1]     = accA[1] + accB[1] + accC[1];
            sG[(m0 + g + 8) * 17 + c]     = accA[2] + accB[2] + accC[2];
            sG[(m0 + g + 8) * 17 + c + 1] = accA[3] + accB[3] + accC[3];
        }
        __syncthreads();

        // gates (1 item/thread)
        {
            const float *bias = (t == 0) ? sBias0 : sBias;
            float pr = sG[gn * 17 + gjj]      + gx_r + bias[gjj];
            float pz = sG[gn * 17 + 4 + gjj]  + gx_z + bias[4 + gjj];
            float pi = sG[gn * 17 + 8 + gjj]  + gx_n + bias[8 + gjj];
            float ph = sG[gn * 17 + 12 + gjj]        + bias[12 + gjj];
            float r = 1.f / (1.f + __expf(-pr));
            float z = 1.f / (1.f + __expf(-pz));
            float ex = __expf(2.f * (pi + r * ph));
            float gg = __fdividef(ex - 1.f, ex + 1.f);
            float hold = __bfloat162float(sHhi[gn * SHP + gj])
                       + __bfloat162float(sHlo[gn * SHP + gj]);
            float hn = (1.f - z) * gg + z * hold;
            __nv_bfloat16 hi, lo;
            split2(hn, hi, lo);
            size_t oidx = (size_t)(t + 1) * (NBAT * KD) + gn * KD + gj;
            g_H_hi[oidx] = hi;
            g_H_lo[oidx] = lo;
        }

        // epoch-broadcast barrier (write-once poll word; self-cleaning)
        __syncthreads();
        if (tid == 0) {
            asm volatile("fence.acq_rel.gpu;\n" ::: "memory");
            unsigned old = atom_add_gpu(&g_cnt[t], 1u);
            if (old == NCTA - 1) {
                st_rel_gpu(&g_ep[t], 1u);
                if (t > 0) { g_cnt[t - 1] = 0u; g_ep[t - 1] = 0u; }
            } else {
                while (ld_acq_gpu(&g_ep[t]) == 0u) { }
            }
        }
        __syncthreads();
    }

    // final cleanup round (replay-idempotent)
    if (tid == 0) {
        unsigned old = atom_add_gpu(&g_fin, 1u);
        if (old == NCTA - 1) {
            g_cnt[TT - 1] = 0u;
            g_ep[TT - 1] = 0u;
            g_fin = 0u;
        }
    }
}

// ---- out[n][t][p] = h_t @ Wp^T + b_p : grid (4,1024) x 256 threads ----
__global__ void __launch_bounds__(256) k_out(const float *__restrict__ bp,
                                             float *__restrict__ out) {
    int w = threadIdx.x >> 5, lane = threadIdx.x & 31;
    int g = lane >> 2, tg = lane & 3;
    int m0 = blockIdx.y * 64 + (w >> 1) * 16;   // m = t*64 + n
    int n0 = blockIdx.x * 64 + (w & 1) * 32;

    float acc[4][4];
#pragma unroll
    for (int i = 0; i < 4; i++)
#pragma unroll
        for (int q = 0; q < 4; q++) acc[i][q] = 0.f;

    const __nv_bfloat16 *a0h = g_H_hi + (size_t)(m0 + g + 64) * KD;
    const __nv_bfloat16 *a1h = g_H_hi + (size_t)(m0 + g + 8 + 64) * KD;
    const __nv_bfloat16 *a0l = g_H_lo + (size_t)(m0 + g + 64) * KD;
    const __nv_bfloat16 *a1l = g_H_lo + (size_t)(m0 + g + 8 + 64) * KD;

#pragma unroll 2
    for (int kc = 0; kc < KD; kc += 16) {
        unsigned ah[4], al[4];
        ah[0] = *(const unsigned *)(a0h + kc + tg * 2);
        ah[1] = *(const unsigned *)(a1h + kc + tg * 2);
        ah[2] = *(const unsigned *)(a0h + kc + tg * 2 + 8);
        ah[3] = *(const unsigned *)(a1h + kc + tg * 2 + 8);
        al[0] = *(const unsigned *)(a0l + kc + tg * 2);
        al[1] = *(const unsigned *)(a1l + kc + tg * 2);
        al[2] = *(const unsigned *)(a0l + kc + tg * 2 + 8);
        al[3] = *(const unsigned *)(a1l + kc + tg * 2 + 8);
#pragma unroll
        for (int nt = 0; nt < 4; nt++) {
            int col = n0 + nt * 8 + g;
            const __nv_bfloat16 *bh = g_Wp_hi + (size_t)col * KD + kc + tg * 2;
            const __nv_bfloat16 *bl = g_Wp_lo + (size_t)col * KD + kc + tg * 2;
            unsigned bhi[2] = { *(const unsigned *)bh, *(const unsigned *)(bh + 8) };
            unsigned blo[2] = { *(const unsigned *)bl, *(const unsigned *)(bl + 8) };
            mma_bf16(acc[nt], ah, bhi);
            mma_bf16(acc[nt], ah, blo);
            mma_bf16(acc[nt], al, bhi);
        }
    }

    int ma = m0 + g, mb = m0 + g + 8;
    size_t ra = (size_t)(ma & 63) * (TT * 256) + (size_t)(ma >> 6) * 256;
    size_t rb = (size_t)(mb & 63) * (TT * 256) + (size_t)(mb >> 6) * 256;
#pragma unroll
    for (int nt = 0; nt < 4; nt++) {
        int col = n0 + nt * 8 + tg * 2;
        float b0 = bp[col], b1 = bp[col + 1];
        *(float2 *)(out + ra + col) = make_float2(acc[nt][0] + b0, acc[nt][1] + b1);
        *(float2 *)(out + rb + col) = make_float2(acc[nt][2] + b0, acc[nt][3] + b1);
    }
}

extern "C" void kernel_launch(void* const* d_in, const int* in_sizes, int n_in,
                              void* d_out, int out_size) {
    const float *X   = (const float *)d_in[0];
    // d_in[1] = text_lengths (all == T; reference ignores them)
    const float *Wih = (const float *)d_in[2];
    const float *Whh = (const float *)d_in[3];
    const float *bih = (const float *)d_in[4];
    const float *bhh = (const float *)d_in[5];
    const float *Wp  = (const float *)d_in[6];
    const float *bp  = (const float *)d_in[7];
    float *out = (float *)d_out;

    static int smem_set = 0;
    if (!smem_set) {
        cudaFuncSetAttribute(k_rec, cudaFuncAttributeMaxDynamicSharedMemorySize, REC_SMEM);
        smem_set = 1;
    }

    int n1 = G3 * KD + G3;
    k_prep1<<<(n1 + 255) / 256, 256>>>(Wih, Wp, bp);

    size_t n2 = (size_t)P0 + P1 + P2 + P3 + P4 + 2 * TT + 1;
    k_prep2<<<(unsigned)((n2 + 255) / 256), 256>>>(Wih, Whh, bih, bhh, Wp, X);

    dim3 ggx(24, 1024);
    k_gx<<<ggx, 256>>>();

    k_rec<<<NCTA, 256, REC_SMEM>>>();

    dim3 gout(4, 1024);
    k_out<<<gout, 256>>>(bp, out);
}